// round 13
// baseline (speedup 1.0000x reference)
#include <cuda_runtime.h>
#include <cuda_fp16.h>
#include <math.h>
#include <stdint.h>

#define SA 136                    // stride (halves) for 128-k tiles
#define S0 56                     // stride (halves) for 48-k tiles
#define PW 108                    // P stride (floats); dim1 at +52; sums at +48
#define BH48H (48 * SA)           // halves per W2 dim tile
#define BD_BYTES (BH48H * 2)      // 13056 bytes per dim

// ---- smem byte offsets ----
#define O_A1H  0u
#define O_A1L  34816u
#define O_W1   69632u
#define O_A0H  69632u
#define O_A0L  83968u
#define O_W0   98304u
#define O_P    0u                 // 128 x 108 f32 = 55296
#define O_B    60416u             // B ring: 4 x 13056 = 52224
#define SM_TOT 112640u

// Pre-converted weights / params (k_prep)
__device__ __half g_w0t[128 * S0];      // W0 n-major [n][k], k<48
__device__ __half g_w1t[128 * SA];      // W1 n-major [n][k], k<128
__device__ __half g_w2s[32 * BH48H];    // W2 tiles per dim, n-major
__device__ float  g_b2p[32 * 48];       // padded b2
__device__ float  g_ab[96];             // BN alpha[48], beta[48]

__device__ __forceinline__ float swishf(float v) {
    return __fdividef(v, 1.0f + __expf(-v));
}

__device__ __forceinline__ void split_fp16(float v, __half* h, __half* l) {
    __half hh = __float2half_rn(v);
    *h = hh;
    *l = __float2half_rn(v - __half2float(hh));
}

__device__ __forceinline__ void mma16816(float* c, const uint32_t* a,
                                         uint32_t b0, uint32_t b1) {
    asm volatile(
        "mma.sync.aligned.m16n8k16.row.col.f32.f16.f16.f32 "
        "{%0,%1,%2,%3}, {%4,%5,%6,%7}, {%8,%9}, {%0,%1,%2,%3};"
        : "+f"(c[0]), "+f"(c[1]), "+f"(c[2]), "+f"(c[3])
        : "r"(a[0]), "r"(a[1]), "r"(a[2]), "r"(a[3]), "r"(b0), "r"(b1));
}

#define LDSM4(d, addr)                                                       \
    asm volatile("ldmatrix.sync.aligned.m8n8.x4.shared.b16 {%0,%1,%2,%3}, [%4];" \
        : "=r"((d)[0]), "=r"((d)[1]), "=r"((d)[2]), "=r"((d)[3]) : "r"(addr))

#define CPASYNC16(dst, src) \
    asm volatile("cp.async.cg.shared.global [%0], [%1], 16;" :: "r"(dst), "l"(src) : "memory")

__device__ __forceinline__ uint32_t smem_u32(const void* p) {
    uint32_t a;
    asm("{ .reg .u64 t; cvta.to.shared.u64 t, %1; cvt.u32.u64 %0, t; }" : "=r"(a) : "l"(p));
    return a;
}

// ---------------------------------------------------------------------------
// Spline for one pair (all 32 lanes: 0-15 -> dim 2jp, 16-31 -> dim 2jp+1).
// Vectorized: 8 x LDS.128 for ew/eh, sums precomputed by the epilogue.
// ---------------------------------------------------------------------------
__device__ __forceinline__ float spline_pair(const float* __restrict__ P,
                                             const float* __restrict__ x,
                                             float* __restrict__ out,
                                             int jp, int jj, int myrow,
                                             size_t grow)
{
    const int j = 2 * jp + jj;
    const float* pr = &P[myrow * PW + jj * 52];
    const float4* pr4 = (const float4*)pr;
    float tin = __ldg(&x[grow * 64 + j]);

    float2 s2 = *(const float2*)&pr[48];          // (sW, sH) from epilogue
    float invW = __fdividef(1.0f, s2.x);
    float invH = __fdividef(1.0f, s2.y);

    float ew[16], eh[16];
    #pragma unroll
    for (int q = 0; q < 4; q++) {
        float4 a4 = pr4[q];
        ew[4 * q + 0] = a4.x; ew[4 * q + 1] = a4.y;
        ew[4 * q + 2] = a4.z; ew[4 * q + 3] = a4.w;
        float4 b4 = pr4[4 + q];
        eh[4 * q + 0] = b4.x; eh[4 * q + 1] = b4.y;
        eh[4 * q + 2] = b4.z; eh[4 * q + 3] = b4.w;
    }

    float tc  = fminf(fmaxf(tin, 0.0f), 1.0f);
    bool  inb = (tin >= 0.0f) && (tin <= 1.0f);

    float xk = 0.0f, cy = 0.0f;
    float xk_b = 0.0f, yk_b = 0.0f;
    float dx_b = ew[0] * invW, dy_b = eh[0] * invH;
    int bidx = 0;
    #pragma unroll
    for (int i = 0; i < 16; i++) {
        float dxi = ew[i] * invW;
        float dyi = eh[i] * invH;
        if (xk <= tc) { bidx = i; xk_b = xk; dx_b = dxi; yk_b = cy; dy_b = dyi; }
        xk += dxi; cy += dyi;
    }

    float v0 = pr[32 + ((bidx > 0) ? bidx - 1 : 0)];
    float v1 = pr[32 + ((bidx < 15) ? bidx : 14)];
    float sp0 = fmaxf(v0, 0.0f) + __logf(1.0f + __expf(-fabsf(v0)));
    float sp1 = fmaxf(v1, 0.0f) + __logf(1.0f + __expf(-fabsf(v1)));
    float d0 = (bidx == 0)  ? 1.0f : sp0;
    float d1 = (bidx == 15) ? 1.0f : sp1;

    float xi   = __fdividef(tc - xk_b, dx_b);
    float s    = __fdividef(dy_b, dx_b);
    float xi1m = xi * (1.0f - xi);
    float den  = s + (d0 + d1 - 2.0f * s) * xi1m;
    float num  = s * xi * xi + d0 * xi1m;
    float y_in = yk_b + dy_b * __fdividef(num, den);
    float omxi = 1.0f - xi;
    float dnum = d1 * xi * xi + 2.0f * s * xi1m + d0 * omxi * omxi;
    float dydx = __fdividef(s * s * dnum, den * den);

    out[grow * 64 + j] = inb ? y_in : tin;
    return inb ? __logf(dydx) : 0.0f;
}

// ---------------------------------------------------------------------------
// Prep: convert all weights to fp16 tiles + BN coefficients + padded bias
// ---------------------------------------------------------------------------
__global__ __launch_bounds__(256)
void k_prep(const float* __restrict__ W0, const float* __restrict__ W1,
            const float* __restrict__ W2, const float* __restrict__ b2,
            const float* __restrict__ bn_scale, const float* __restrict__ bn_bias,
            const float* __restrict__ bn_mean, const float* __restrict__ bn_var)
{
    int idx = blockIdx.x * 256 + threadIdx.x;
    if (idx < 32 * BH48H) {              // W2 tiles
        int j = idx / BH48H;
        int rem = idx - j * BH48H;
        int n = rem / SA;
        int k = rem - n * SA;
        float v = (n < 47 && k < 128) ? W2[(size_t)k * 1504 + j * 47 + n] : 0.0f;
        g_w2s[idx] = __float2half_rn(v);
    }
    if (idx < 128 * SA) {                // W1 tile
        int n = idx / SA, k = idx - n * SA;
        g_w1t[idx] = (k < 128) ? __float2half_rn(W1[(size_t)k * 128 + n]) : __float2half_rn(0.0f);
    }
    if (idx < 128 * S0) {                // W0 tile
        int n = idx / S0, k = idx - n * S0;
        g_w0t[idx] = (k < 48) ? __float2half_rn(W0[(size_t)k * 128 + n]) : __float2half_rn(0.0f);
    }
    if (idx < 32 * 48) {                 // padded b2
        int j = idx / 48, cc = idx - j * 48;
        g_b2p[idx] = (cc < 47) ? b2[j * 47 + cc] : 0.0f;
    }
    if (idx < 48) {                      // BN coefficients
        float a = bn_scale[idx] * rsqrtf(bn_var[idx] + 1e-5f);
        g_ab[idx]      = a;
        g_ab[48 + idx] = bn_bias[idx] - bn_mean[idx] * a;
    }
}

// ---------------------------------------------------------------------------
// Fused kernel. Epilogue computes sW/sH via quad shuffles; spline reads P
// with float4 loads. Sync skeleton identical to round 10/12 (proven safe).
// ---------------------------------------------------------------------------
__global__ __launch_bounds__(256, 2)
void k_fused(const float* __restrict__ x, const float* __restrict__ c,
             const float* __restrict__ b0, const float* __restrict__ b1,
             float* __restrict__ out, int N)
{
    extern __shared__ char smem[];
    const uint32_t sb = smem_u32(smem);

    const int tid  = threadIdx.x;
    const int warp = tid >> 5;
    const int lane = tid & 31;
    const int g    = lane >> 2;
    const int c2   = lane & 3;
    const int r0   = warp * 16;
    const int row0 = blockIdx.x * 128;

    // ---- W0 cp.async (896 x 16B)
    {
        const char* src = (const char*)g_w0t;
        #pragma unroll
        for (int it = 0; it < 4; it++) {
            int ch = tid + it * 256;
            if (ch < 896) CPASYNC16(sb + O_W0 + ch * 16, src + ch * 16);
        }
        asm volatile("cp.async.commit_group;" ::: "memory");
    }

    // ---- Stage A0 (BN'd [xc|c]), warp-local rows, fp16 hi/lo; copy xc -> out
    {
        __half* A0h = (__half*)(smem + O_A0H);
        __half* A0l = (__half*)(smem + O_A0L);
        for (int i = lane; i < 16 * 48; i += 32) {
            int r = i / 48, k = i - (i / 48) * 48;
            size_t rg = (size_t)(row0 + r0 + r);
            float v;
            if (k < 32) { v = x[rg * 64 + 32 + k]; out[rg * 64 + 32 + k] = v; }
            else        { v = c[rg * 16 + (k - 32)]; }
            float a = v * g_ab[k] + g_ab[48 + k];
            __half h, l;
            split_fp16(a, &h, &l);
            A0h[(r0 + r) * S0 + k] = h;
            A0l[(r0 + r) * S0 + k] = l;
        }
    }
    asm volatile("cp.async.wait_group 0;" ::: "memory");
    __syncthreads();   // W0 + all A0 rows visible

    // Fragment address components
    const uint32_t a0_off  = (uint32_t)(((r0 + (lane & 15)) * S0 + ((lane >> 4) << 3)) * 2);
    const uint32_t a1_off  = (uint32_t)(((r0 + (lane & 15)) * SA + ((lane >> 4) << 3)) * 2);
    const uint32_t bn0_off = (uint32_t)((((lane & 7) + ((lane >> 4) << 3)) * S0) * 2 + (((lane >> 3) & 1) << 4));
    const uint32_t bn1_off = (uint32_t)((((lane & 7) + ((lane >> 4) << 3)) * SA) * 2 + (((lane >> 3) & 1) << 4));

    // ================= L0: h1 = swish(A0 @ W0 + b0) =====
    {
        float acc[16][4];
        #pragma unroll
        for (int t = 0; t < 16; t++)
            #pragma unroll
            for (int q = 0; q < 4; q++) acc[t][q] = 0.0f;

        const uint32_t a0h_addr = sb + O_A0H + a0_off;
        const uint32_t a0l_addr = sb + O_A0L + a0_off;
        const uint32_t w0_base  = sb + O_W0 + bn0_off;

        #pragma unroll
        for (int ks = 0; ks < 3; ks++) {
            uint32_t ah[4], al[4];
            LDSM4(ah, a0h_addr + ks * 32);
            LDSM4(al, a0l_addr + ks * 32);
            #pragma unroll
            for (int t2 = 0; t2 < 8; t2++) {
                uint32_t bw[4];
                LDSM4(bw, w0_base + t2 * 16 * S0 * 2 + ks * 32);
                mma16816(acc[2 * t2],     ah, bw[0], bw[1]);
                mma16816(acc[2 * t2],     al, bw[0], bw[1]);
                mma16816(acc[2 * t2 + 1], ah, bw[2], bw[3]);
                mma16816(acc[2 * t2 + 1], al, bw[2], bw[3]);
            }
        }

        __half* A1h = (__half*)(smem + O_A1H);
        __half* A1l = (__half*)(smem + O_A1L);
        #pragma unroll
        for (int t = 0; t < 16; t++) {
            int cb = 8 * t + 2 * c2;
            float2 bb = __ldg((const float2*)&b0[cb]);
            float v00 = swishf(acc[t][0] + bb.x), v01 = swishf(acc[t][1] + bb.y);
            float v10 = swishf(acc[t][2] + bb.x), v11 = swishf(acc[t][3] + bb.y);
            __half h0, l0, h1, l1;
            split_fp16(v00, &h0, &l0); split_fp16(v01, &h1, &l1);
            *(__half2*)&A1h[(r0 + g) * SA + cb] = __halves2half2(h0, h1);
            *(__half2*)&A1l[(r0 + g) * SA + cb] = __halves2half2(l0, l1);
            split_fp16(v10, &h0, &l0); split_fp16(v11, &h1, &l1);
            *(__half2*)&A1h[(r0 + g + 8) * SA + cb] = __halves2half2(h0, h1);
            *(__half2*)&A1l[(r0 + g + 8) * SA + cb] = __halves2half2(l0, l1);
        }
    }
    __syncthreads();   // all warps done with A0/W0 region

    // ---- W1 cp.async into (dead) A0/W0 region (2176 x 16B)
    {
        const char* src = (const char*)g_w1t;
        #pragma unroll
        for (int it = 0; it < 9; it++) {
            int ch = tid + it * 256;
            if (ch < 2176) CPASYNC16(sb + O_W1 + ch * 16, src + ch * 16);
        }
        asm volatile("cp.async.commit_group;" ::: "memory");
        asm volatile("cp.async.wait_group 0;" ::: "memory");
    }
    __syncthreads();

    // ================= L1: h2 = swish(A1 @ W1 + b1), K=128 ==================
    uint32_t afh[8][4];    // h2-hi fragments (sole A operand of the W2 GEMM)
    {
        float acc[16][4];
        #pragma unroll
        for (int t = 0; t < 16; t++)
            #pragma unroll
            for (int q = 0; q < 4; q++) acc[t][q] = 0.0f;

        const uint32_t a1h_addr = sb + O_A1H + a1_off;
        const uint32_t a1l_addr = sb + O_A1L + a1_off;
        const uint32_t w1_base  = sb + O_W1 + bn1_off;

        #pragma unroll
        for (int ks = 0; ks < 8; ks++) {
            uint32_t ah[4], al[4];
            LDSM4(ah, a1h_addr + ks * 32);
            LDSM4(al, a1l_addr + ks * 32);
            #pragma unroll
            for (int t2 = 0; t2 < 8; t2++) {
                uint32_t bw[4];
                LDSM4(bw, w1_base + t2 * 16 * SA * 2 + ks * 32);
                mma16816(acc[2 * t2],     ah, bw[0], bw[1]);
                mma16816(acc[2 * t2],     al, bw[0], bw[1]);
                mma16816(acc[2 * t2 + 1], ah, bw[2], bw[3]);
                mma16816(acc[2 * t2 + 1], al, bw[2], bw[3]);
            }
        }
        __syncwarp();   // own A1 rows consumed; safe to overwrite (warp-local)

        // Epilogue: h2-hi only -> staging in O_A1L region
        __half* H2h = (__half*)(smem + O_A1L);
        #pragma unroll
        for (int t = 0; t < 16; t++) {
            int cb = 8 * t + 2 * c2;
            float2 bb = __ldg((const float2*)&b1[cb]);
            float v00 = swishf(acc[t][0] + bb.x), v01 = swishf(acc[t][1] + bb.y);
            float v10 = swishf(acc[t][2] + bb.x), v11 = swishf(acc[t][3] + bb.y);
            *(__half2*)&H2h[(r0 + g) * SA + cb] =
                __halves2half2(__float2half_rn(v00), __float2half_rn(v01));
            *(__half2*)&H2h[(r0 + g + 8) * SA + cb] =
                __halves2half2(__float2half_rn(v10), __float2half_rn(v11));
        }
        __syncwarp();

        const uint32_t h2h_addr = sb + O_A1L + a1_off;
        #pragma unroll
        for (int ks = 0; ks < 8; ks++)
            LDSM4(afh[ks], h2h_addr + ks * 32);
    }
    __syncthreads();   // staging / W1 dead; P and B regions free

    // ================= W2 GEMM + software-pipelined spline ==================
    const uint32_t sbB = sb + O_B;
    float* P = (float*)(smem + O_P);

    // Prologue: prefetch pair 0 (dims 0,1) as one group
    {
        #pragma unroll
        for (int dd = 0; dd < 2; dd++) {
            uint32_t bdst = sbB + (uint32_t)dd * BD_BYTES;
            const char* bsrc = (const char*)(g_w2s + (size_t)dd * BH48H);
            #pragma unroll
            for (int it = 0; it < 4; it++) {
                int ch = tid + it * 256;
                if (ch < 816) CPASYNC16(bdst + ch * 16, bsrc + ch * 16);
            }
        }
        asm volatile("cp.async.commit_group;" ::: "memory");
    }

    const uint32_t b_off = bn1_off;
    const int jj = lane >> 4;               // 0: dim j0, 1: dim j1 (spline half)
    const int myrow = r0 + (lane & 15);
    const size_t grow = (size_t)(row0 + myrow);

    float logdet = 0.0f;

    for (int jp = 0; jp < 16; jp++) {
        // Own copies of pair jp done, then publish all threads' copies and
        // retire pair jp-1 GEMM reads before its slots are overwritten.
        asm volatile("cp.async.wait_group 0;" ::: "memory");
        __syncthreads();

        if (jp < 15) {
            #pragma unroll
            for (int dd = 0; dd < 2; dd++) {
                int dim = 2 * jp + 2 + dd;
                uint32_t bdst = sbB + (uint32_t)(dim & 3) * BD_BYTES;
                const char* bsrc = (const char*)(g_w2s + (size_t)dim * BH48H);
                #pragma unroll
                for (int it = 0; it < 4; it++) {
                    int ch = tid + it * 256;
                    if (ch < 816) CPASYNC16(bdst + ch * 16, bsrc + ch * 16);
                }
            }
            asm volatile("cp.async.commit_group;" ::: "memory");
        }

        // ---- GEMM dim j0
        const int j0 = 2 * jp;
        float acc0[6][4];
        #pragma unroll
        for (int t = 0; t < 6; t++)
            #pragma unroll
            for (int q = 0; q < 4; q++) acc0[t][q] = 0.0f;
        {
            const uint32_t bh_base = sbB + (uint32_t)(j0 & 3) * BD_BYTES + b_off;
            #pragma unroll
            for (int ks = 0; ks < 8; ks++) {
                uint32_t bh[3][4];
                #pragma unroll
                for (int t2 = 0; t2 < 3; t2++) {
                    uint32_t o = (uint32_t)(t2 * 16 * SA * 2 + ks * 32);
                    LDSM4(bh[t2], bh_base + o);
                }
                #pragma unroll
                for (int t2 = 0; t2 < 3; t2++) {
                    mma16816(acc0[2 * t2],     afh[ks], bh[t2][0], bh[t2][1]);
                    mma16816(acc0[2 * t2 + 1], afh[ks], bh[t2][2], bh[t2][3]);
                }
            }
        }

        // ---- Spline for the PREVIOUS pair, overlapping j0's in-flight MMAs
        if (jp > 0)
            logdet += spline_pair(P, x, out, jp - 1, jj, myrow, grow);
        __syncwarp();   // P(jp-1) reads retired before epilogues overwrite P

        // ---- GEMM dim j1
        const int j1 = 2 * jp + 1;
        float acc1[6][4];
        #pragma unroll
        for (int t = 0; t < 6; t++)
            #pragma unroll
            for (int q = 0; q < 4; q++) acc1[t][q] = 0.0f;
        {
            const uint32_t bh_base = sbB + (uint32_t)(j1 & 3) * BD_BYTES + b_off;
            #pragma unroll
            for (int ks = 0; ks < 8; ks++) {
                uint32_t bh[3][4];
                #pragma unroll
                for (int t2 = 0; t2 < 3; t2++) {
                    uint32_t o = (uint32_t)(t2 * 16 * SA * 2 + ks * 32);
                    LDSM4(bh[t2], bh_base + o);
                }
                #pragma unroll
                for (int t2 = 0; t2 < 3; t2++) {
                    mma16816(acc1[2 * t2],     afh[ks], bh[t2][0], bh[t2][1]);
                    mma16816(acc1[2 * t2 + 1], afh[ks], bh[t2][2], bh[t2][3]);
                }
            }
        }

        // ---- Epilogues (bias, exp, partial sums, quad-reduced sW/sH) -> P
        #pragma unroll
        for (int dd = 0; dd < 2; dd++) {
            const int j = 2 * jp + dd;
            const int co = dd * 52;
            const float* bj = &g_b2p[j * 48];
            float (*acc)[4] = dd ? acc1 : acc0;

            float swA = 0.0f, shA = 0.0f, swB = 0.0f, shB = 0.0f;
            #pragma unroll
            for (int t = 0; t < 6; t++) {
                int cb = 8 * t + 2 * c2;
                float2 bb = *(const float2*)&bj[cb];
                float v00 = acc[t][0] + bb.x, v01 = acc[t][1] + bb.y;
                float v10 = acc[t][2] + bb.x, v11 = acc[t][3] + bb.y;
                if (t < 4) {
                    v00 = __expf(v00); v01 = __expf(v01);
                    v10 = __expf(v10); v11 = __expf(v11);
                    if (t < 2) { swA += v00 + v01; swB += v10 + v11; }
                    else       { shA += v00 + v01; shB += v10 + v11; }
                }
                *(float2*)&P[(r0 + g) * PW + co + cb]     = make_float2(v00, v01);
                *(float2*)&P[(r0 + g + 8) * PW + co + cb] = make_float2(v10, v11);
            }
            // quad-reduce over c2 (lanes 4g..4g+3)
            swA += __shfl_xor_sync(0xffffffffu, swA, 1);
            swA += __shfl_xor_sync(0xffffffffu, swA, 2);
            shA += __shfl_xor_sync(0xffffffffu, shA, 1);
            shA += __shfl_xor_sync(0xffffffffu, shA, 2);
            swB += __shfl_xor_sync(0xffffffffu, swB, 1);
            swB += __shfl_xor_sync(0xffffffffu, swB, 2);
            shB += __shfl_xor_sync(0xffffffffu, shB, 1);
            shB += __shfl_xor_sync(0xffffffffu, shB, 2);
            if (c2 == 0) {
                *(float2*)&P[(r0 + g) * PW + co + 48]     = make_float2(swA, shA);
                *(float2*)&P[(r0 + g + 8) * PW + co + 48] = make_float2(swB, shB);
            }
        }
        __syncwarp();   // P(jp) visible to spline next iteration
    }

    // Drain: spline for the last pair
    logdet += spline_pair(P, x, out, 15, jj, myrow, grow);

    // Combine the two half-warp logdet partials and store.
    logdet += __shfl_down_sync(0xffffffffu, logdet, 16);
    if (lane < 16)
        out[(size_t)N * 64 + row0 + myrow] = logdet;
}

// ---------------------------------------------------------------------------
extern "C" void kernel_launch(void* const* d_in, const int* in_sizes, int n_in,
                              void* d_out, int out_size)
{
    const float* x  = (const float*)d_in[0];
    const float* c  = (const float*)d_in[1];
    const float* bs = (const float*)d_in[2];
    const float* bb = (const float*)d_in[3];
    const float* bm = (const float*)d_in[4];
    const float* bv = (const float*)d_in[5];
    const float* W0 = (const float*)d_in[6];
    const float* b0 = (const float*)d_in[7];
    const float* W1 = (const float*)d_in[8];
    const float* b1 = (const float*)d_in[9];
    const float* W2 = (const float*)d_in[10];
    const float* b2 = (const float*)d_in[11];
    float* out = (float*)d_out;

    int N = in_sizes[0] / 64;

    cudaFuncSetAttribute(k_fused, cudaFuncAttributeMaxDynamicSharedMemorySize, (int)SM_TOT);

    k_prep<<<(32 * BH48H + 255) / 256, 256>>>(W0, W1, W2, b2, bs, bb, bm, bv);
    k_fused<<<N / 128, 256, SM_TOT>>>(x, c, b0, b1, out, N);
}

// round 15
// speedup vs baseline: 1.0628x; 1.0628x over previous
#include <cuda_runtime.h>
#include <cuda_fp16.h>
#include <math.h>
#include <stdint.h>

#define SA 136                    // stride (halves) for 128-k tiles
#define S0 56                     // stride (halves) for 48-k tiles
#define PW 108                    // P stride (floats); dim1 at +52

// ---- smem byte offsets ----
#define O_A1H  0u
#define O_A1L  34816u
#define O_W1   69632u
#define O_A0H  69632u
#define O_A0L  83968u
#define O_W0   98304u             // W0 staging ends at 112640
#define O_P    0u                 // 128 x 108 f32 = 55296 (overlays dead A1H/A1L)
#define SM_TOT 112640u

// Pre-converted weights / params (k_prep)
__device__ __half g_w0t[128 * S0];      // W0 n-major [n][k], k<48
__device__ __half g_w1t[128 * SA];      // W1 n-major [n][k], k<128
// W2 in mma-fragment-major order: per dim j (32): 8 ks x 3 tile-pairs x 32
// lanes x 8 halves (16B). One LDG.128 per lane = the 4 B-regs of 2 n-tiles.
__device__ __align__(16) __half g_w2f[32 * 6144];
__device__ float  g_b2p[32 * 48];       // padded b2
__device__ float  g_ab[96];             // BN alpha[48], beta[48]

__device__ __forceinline__ float swishf(float v) {
    return __fdividef(v, 1.0f + __expf(-v));
}

__device__ __forceinline__ void split_fp16(float v, __half* h, __half* l) {
    __half hh = __float2half_rn(v);
    *h = hh;
    *l = __float2half_rn(v - __half2float(hh));
}

__device__ __forceinline__ void mma16816(float* c, const uint32_t* a,
                                         uint32_t b0, uint32_t b1) {
    asm volatile(
        "mma.sync.aligned.m16n8k16.row.col.f32.f16.f16.f32 "
        "{%0,%1,%2,%3}, {%4,%5,%6,%7}, {%8,%9}, {%0,%1,%2,%3};"
        : "+f"(c[0]), "+f"(c[1]), "+f"(c[2]), "+f"(c[3])
        : "r"(a[0]), "r"(a[1]), "r"(a[2]), "r"(a[3]), "r"(b0), "r"(b1));
}

#define LDSM4(d, addr)                                                       \
    asm volatile("ldmatrix.sync.aligned.m8n8.x4.shared.b16 {%0,%1,%2,%3}, [%4];" \
        : "=r"((d)[0]), "=r"((d)[1]), "=r"((d)[2]), "=r"((d)[3]) : "r"(addr))

#define CPASYNC16(dst, src) \
    asm volatile("cp.async.cg.shared.global [%0], [%1], 16;" :: "r"(dst), "l"(src) : "memory")

__device__ __forceinline__ uint32_t smem_u32(const void* p) {
    uint32_t a;
    asm("{ .reg .u64 t; cvta.to.shared.u64 t, %1; cvt.u32.u64 %0, t; }" : "=r"(a) : "l"(p));
    return a;
}

// ---------------------------------------------------------------------------
// Spline for one pair (all 32 lanes: 0-15 -> dim 2jp, 16-31 -> dim 2jp+1).
// float4 loads for ew/eh; sums computed in registers (round-12 order).
// ---------------------------------------------------------------------------
__device__ __forceinline__ float spline_pair(const float* __restrict__ P,
                                             const float* __restrict__ x,
                                             float* __restrict__ out,
                                             int jp, int jj, int myrow,
                                             size_t grow)
{
    const int j = 2 * jp + jj;
    const float* pr = &P[myrow * PW + jj * 52];
    const float4* pr4 = (const float4*)pr;
    float tin = __ldg(&x[grow * 64 + j]);

    float ew[16], eh[16];
    #pragma unroll
    for (int q = 0; q < 4; q++) {
        float4 a4 = pr4[q];
        ew[4 * q + 0] = a4.x; ew[4 * q + 1] = a4.y;
        ew[4 * q + 2] = a4.z; ew[4 * q + 3] = a4.w;
        float4 b4 = pr4[4 + q];
        eh[4 * q + 0] = b4.x; eh[4 * q + 1] = b4.y;
        eh[4 * q + 2] = b4.z; eh[4 * q + 3] = b4.w;
    }

    float sW = 0.0f, sH = 0.0f;
    #pragma unroll
    for (int i = 0; i < 16; i++) { sW += ew[i]; sH += eh[i]; }
    float invW = __fdividef(1.0f, sW);
    float invH = __fdividef(1.0f, sH);

    float tc  = fminf(fmaxf(tin, 0.0f), 1.0f);
    bool  inb = (tin >= 0.0f) && (tin <= 1.0f);

    float xk = 0.0f, cy = 0.0f;
    float xk_b = 0.0f, yk_b = 0.0f;
    float dx_b = ew[0] * invW, dy_b = eh[0] * invH;
    int bidx = 0;
    #pragma unroll
    for (int i = 0; i < 16; i++) {
        float dxi = ew[i] * invW;
        float dyi = eh[i] * invH;
        if (xk <= tc) { bidx = i; xk_b = xk; dx_b = dxi; yk_b = cy; dy_b = dyi; }
        xk += dxi; cy += dyi;
    }

    float v0 = pr[32 + ((bidx > 0) ? bidx - 1 : 0)];
    float v1 = pr[32 + ((bidx < 15) ? bidx : 14)];
    float sp0 = fmaxf(v0, 0.0f) + __logf(1.0f + __expf(-fabsf(v0)));
    float sp1 = fmaxf(v1, 0.0f) + __logf(1.0f + __expf(-fabsf(v1)));
    float d0 = (bidx == 0)  ? 1.0f : sp0;
    float d1 = (bidx == 15) ? 1.0f : sp1;

    float xi   = __fdividef(tc - xk_b, dx_b);
    float s    = __fdividef(dy_b, dx_b);
    float xi1m = xi * (1.0f - xi);
    float den  = s + (d0 + d1 - 2.0f * s) * xi1m;
    float num  = s * xi * xi + d0 * xi1m;
    float y_in = yk_b + dy_b * __fdividef(num, den);
    float omxi = 1.0f - xi;
    float dnum = d1 * xi * xi + 2.0f * s * xi1m + d0 * omxi * omxi;
    float dydx = __fdividef(s * s * dnum, den * den);

    out[grow * 64 + j] = inb ? y_in : tin;
    return inb ? __logf(dydx) : 0.0f;
}

// ---------------------------------------------------------------------------
// Prep: W0/W1 fp16 tiles, W2 fragment-major fp16, BN coeffs, padded bias
// ---------------------------------------------------------------------------
__global__ __launch_bounds__(256)
void k_prep(const float* __restrict__ W0, const float* __restrict__ W1,
            const float* __restrict__ W2, const float* __restrict__ b2,
            const float* __restrict__ bn_scale, const float* __restrict__ bn_bias,
            const float* __restrict__ bn_mean, const float* __restrict__ bn_var)
{
    int idx = blockIdx.x * 256 + threadIdx.x;
    if (idx < 32 * 6144) {               // W2 fragment-major
        int j   = idx / 6144;
        int r   = idx - j * 6144;
        int ks  = r / 768;
        int r2  = r - ks * 768;
        int tp  = r2 / 256;
        int r3  = r2 - tp * 256;
        int ln  = r3 >> 3;
        int h   = r3 & 7;
        int n   = tp * 16 + (ln >> 2) + ((h >= 4) ? 8 : 0);
        int kk  = ks * 16 + 2 * (ln & 3) + (h & 1) + (((h >> 1) & 1) << 3);
        float v = (n < 47) ? W2[(size_t)kk * 1504 + j * 47 + n] : 0.0f;
        g_w2f[idx] = __float2half_rn(v);
    }
    if (idx < 128 * SA) {                // W1 tile
        int n = idx / SA, k = idx - n * SA;
        g_w1t[idx] = (k < 128) ? __float2half_rn(W1[(size_t)k * 128 + n]) : __float2half_rn(0.0f);
    }
    if (idx < 128 * S0) {                // W0 tile
        int n = idx / S0, k = idx - n * S0;
        g_w0t[idx] = (k < 48) ? __float2half_rn(W0[(size_t)k * 128 + n]) : __float2half_rn(0.0f);
    }
    if (idx < 32 * 48) {                 // padded b2
        int j = idx / 48, cc = idx - j * 48;
        g_b2p[idx] = (cc < 47) ? b2[j * 47 + cc] : 0.0f;
    }
    if (idx < 48) {                      // BN coefficients
        float a = bn_scale[idx] * rsqrtf(bn_var[idx] + 1e-5f);
        g_ab[idx]      = a;
        g_ab[48 + idx] = bn_bias[idx] - bn_mean[idx] * a;
    }
}

// ---------------------------------------------------------------------------
// Fused kernel: BN + MLP (fp16 HMMA) + W2 GEMM (B fragments via LDG from
// fragment-major global; NO block barriers in the loop) + dual-dim spline.
// Block = 128 rows, 256 threads (8 warps x 16 rows), 2 blocks/SM.
// ---------------------------------------------------------------------------
__global__ __launch_bounds__(256, 2)
void k_fused(const float* __restrict__ x, const float* __restrict__ c,
             const float* __restrict__ b0, const float* __restrict__ b1,
             float* __restrict__ out, int N)
{
    extern __shared__ char smem[];
    const uint32_t sb = smem_u32(smem);

    const int tid  = threadIdx.x;
    const int warp = tid >> 5;
    const int lane = tid & 31;
    const int g    = lane >> 2;
    const int c2   = lane & 3;
    const int r0   = warp * 16;
    const int row0 = blockIdx.x * 128;

    // ---- W0 cp.async (896 x 16B)
    {
        const char* src = (const char*)g_w0t;
        #pragma unroll
        for (int it = 0; it < 4; it++) {
            int ch = tid + it * 256;
            if (ch < 896) CPASYNC16(sb + O_W0 + ch * 16, src + ch * 16);
        }
        asm volatile("cp.async.commit_group;" ::: "memory");
    }

    // ---- Stage A0 (BN'd [xc|c]), warp-local rows, fp16 hi/lo; copy xc -> out
    {
        __half* A0h = (__half*)(smem + O_A0H);
        __half* A0l = (__half*)(smem + O_A0L);
        for (int i = lane; i < 16 * 48; i += 32) {
            int r = i / 48, k = i - (i / 48) * 48;
            size_t rg = (size_t)(row0 + r0 + r);
            float v;
            if (k < 32) { v = x[rg * 64 + 32 + k]; out[rg * 64 + 32 + k] = v; }
            else        { v = c[rg * 16 + (k - 32)]; }
            float a = v * g_ab[k] + g_ab[48 + k];
            __half h, l;
            split_fp16(a, &h, &l);
            A0h[(r0 + r) * S0 + k] = h;
            A0l[(r0 + r) * S0 + k] = l;
        }
    }
    asm volatile("cp.async.wait_group 0;" ::: "memory");
    __syncthreads();   // W0 + all A0 rows visible

    // Fragment address components
    const uint32_t a0_off  = (uint32_t)(((r0 + (lane & 15)) * S0 + ((lane >> 4) << 3)) * 2);
    const uint32_t a1_off  = (uint32_t)(((r0 + (lane & 15)) * SA + ((lane >> 4) << 3)) * 2);
    const uint32_t bn0_off = (uint32_t)((((lane & 7) + ((lane >> 4) << 3)) * S0) * 2 + (((lane >> 3) & 1) << 4));
    const uint32_t bn1_off = (uint32_t)((((lane & 7) + ((lane >> 4) << 3)) * SA) * 2 + (((lane >> 3) & 1) << 4));

    // ================= L0: h1 = swish(A0 @ W0 + b0) =====
    {
        float acc[16][4];
        #pragma unroll
        for (int t = 0; t < 16; t++)
            #pragma unroll
            for (int q = 0; q < 4; q++) acc[t][q] = 0.0f;

        const uint32_t a0h_addr = sb + O_A0H + a0_off;
        const uint32_t a0l_addr = sb + O_A0L + a0_off;
        const uint32_t w0_base  = sb + O_W0 + bn0_off;

        #pragma unroll
        for (int ks = 0; ks < 3; ks++) {
            uint32_t ah[4], al[4];
            LDSM4(ah, a0h_addr + ks * 32);
            LDSM4(al, a0l_addr + ks * 32);
            #pragma unroll
            for (int t2 = 0; t2 < 8; t2++) {
                uint32_t bw[4];
                LDSM4(bw, w0_base + t2 * 16 * S0 * 2 + ks * 32);
                mma16816(acc[2 * t2],     ah, bw[0], bw[1]);
                mma16816(acc[2 * t2],     al, bw[0], bw[1]);
                mma16816(acc[2 * t2 + 1], ah, bw[2], bw[3]);
                mma16816(acc[2 * t2 + 1], al, bw[2], bw[3]);
            }
        }

        __half* A1h = (__half*)(smem + O_A1H);
        __half* A1l = (__half*)(smem + O_A1L);
        #pragma unroll
        for (int t = 0; t < 16; t++) {
            int cb = 8 * t + 2 * c2;
            float2 bb = __ldg((const float2*)&b0[cb]);
            float v00 = swishf(acc[t][0] + bb.x), v01 = swishf(acc[t][1] + bb.y);
            float v10 = swishf(acc[t][2] + bb.x), v11 = swishf(acc[t][3] + bb.y);
            __half h0, l0, h1, l1;
            split_fp16(v00, &h0, &l0); split_fp16(v01, &h1, &l1);
            *(__half2*)&A1h[(r0 + g) * SA + cb] = __halves2half2(h0, h1);
            *(__half2*)&A1l[(r0 + g) * SA + cb] = __halves2half2(l0, l1);
            split_fp16(v10, &h0, &l0); split_fp16(v11, &h1, &l1);
            *(__half2*)&A1h[(r0 + g + 8) * SA + cb] = __halves2half2(h0, h1);
            *(__half2*)&A1l[(r0 + g + 8) * SA + cb] = __halves2half2(l0, l1);
        }
    }
    __syncthreads();   // all warps done with A0/W0 region

    // ---- W1 cp.async into (dead) A0/W0 region (2176 x 16B)
    {
        const char* src = (const char*)g_w1t;
        #pragma unroll
        for (int it = 0; it < 9; it++) {
            int ch = tid + it * 256;
            if (ch < 2176) CPASYNC16(sb + O_W1 + ch * 16, src + ch * 16);
        }
        asm volatile("cp.async.commit_group;" ::: "memory");
        asm volatile("cp.async.wait_group 0;" ::: "memory");
    }
    __syncthreads();

    // ================= L1: h2 = swish(A1 @ W1 + b1), K=128 ==================
    uint32_t afh[8][4];    // h2-hi fragments (sole A operand of the W2 GEMM)
    {
        float acc[16][4];
        #pragma unroll
        for (int t = 0; t < 16; t++)
            #pragma unroll
            for (int q = 0; q < 4; q++) acc[t][q] = 0.0f;

        const uint32_t a1h_addr = sb + O_A1H + a1_off;
        const uint32_t a1l_addr = sb + O_A1L + a1_off;
        const uint32_t w1_base  = sb + O_W1 + bn1_off;

        #pragma unroll
        for (int ks = 0; ks < 8; ks++) {
            uint32_t ah[4], al[4];
            LDSM4(ah, a1h_addr + ks * 32);
            LDSM4(al, a1l_addr + ks * 32);
            #pragma unroll
            for (int t2 = 0; t2 < 8; t2++) {
                uint32_t bw[4];
                LDSM4(bw, w1_base + t2 * 16 * SA * 2 + ks * 32);
                mma16816(acc[2 * t2],     ah, bw[0], bw[1]);
                mma16816(acc[2 * t2],     al, bw[0], bw[1]);
                mma16816(acc[2 * t2 + 1], ah, bw[2], bw[3]);
                mma16816(acc[2 * t2 + 1], al, bw[2], bw[3]);
            }
        }
        __syncwarp();   // own A1 rows consumed; safe to overwrite (warp-local)

        // Epilogue: h2-hi only -> staging in O_A1L region
        __half* H2h = (__half*)(smem + O_A1L);
        #pragma unroll
        for (int t = 0; t < 16; t++) {
            int cb = 8 * t + 2 * c2;
            float2 bb = __ldg((const float2*)&b1[cb]);
            float v00 = swishf(acc[t][0] + bb.x), v01 = swishf(acc[t][1] + bb.y);
            float v10 = swishf(acc[t][2] + bb.x), v11 = swishf(acc[t][3] + bb.y);
            *(__half2*)&H2h[(r0 + g) * SA + cb] =
                __halves2half2(__float2half_rn(v00), __float2half_rn(v01));
            *(__half2*)&H2h[(r0 + g + 8) * SA + cb] =
                __halves2half2(__float2half_rn(v10), __float2half_rn(v11));
        }
        __syncwarp();

        const uint32_t h2h_addr = sb + O_A1L + a1_off;
        #pragma unroll
        for (int ks = 0; ks < 8; ks++)
            LDSM4(afh[ks], h2h_addr + ks * 32);
    }
    __syncthreads();   // staging/W1 dead; P region free. LAST block barrier.

    // ================= W2 GEMM + spline loop (no block barriers) ============
    float* P = (float*)(smem + O_P);
    const uint4* w2f = (const uint4*)g_w2f;   // [j][ks][tp][lane] 16B units

    const int jj = lane >> 4;               // 0: dim j0, 1: dim j1 (spline half)
    const int myrow = r0 + (lane & 15);
    const size_t grow = (size_t)(row0 + myrow);

    float logdet = 0.0f;

    for (int jp = 0; jp < 16; jp++) {
        // ---- Two GEMMs + epilogues (B fragments straight from global/L1)
        #pragma unroll
        for (int dd = 0; dd < 2; dd++) {
            const int j = 2 * jp + dd;
            const uint4* bp = w2f + (size_t)j * 768 + lane;

            float acc[6][4];
            #pragma unroll
            for (int t = 0; t < 6; t++)
                #pragma unroll
                for (int q = 0; q < 4; q++) acc[t][q] = 0.0f;

            #pragma unroll
            for (int ks = 0; ks < 8; ks++) {
                uint4 q0 = __ldg(bp + (ks * 3 + 0) * 32);
                uint4 q1 = __ldg(bp + (ks * 3 + 1) * 32);
                uint4 q2 = __ldg(bp + (ks * 3 + 2) * 32);
                mma16816(acc[0], afh[ks], q0.x, q0.y);
                mma16816(acc[1], afh[ks], q0.z, q0.w);
                mma16816(acc[2], afh[ks], q1.x, q1.y);
                mma16816(acc[3], afh[ks], q1.z, q1.w);
                mma16816(acc[4], afh[ks], q2.x, q2.y);
                mma16816(acc[5], afh[ks], q2.z, q2.w);
            }

            // Epilogue: bias, exp for softmax cols (<32); dim dd at +52 cols
            const float* bj = &g_b2p[j * 48];
            const int co = dd * 52;
            #pragma unroll
            for (int t = 0; t < 6; t++) {
                int cb = 8 * t + 2 * c2;
                float2 bb = *(const float2*)&bj[cb];
                float v00 = acc[t][0] + bb.x, v01 = acc[t][1] + bb.y;
                float v10 = acc[t][2] + bb.x, v11 = acc[t][3] + bb.y;
                if (t < 4) {
                    v00 = __expf(v00); v01 = __expf(v01);
                    v10 = __expf(v10); v11 = __expf(v11);
                }
                *(float2*)&P[(r0 + g) * PW + co + cb]     = make_float2(v00, v01);
                *(float2*)&P[(r0 + g + 8) * PW + co + cb] = make_float2(v10, v11);
            }
        }
        __syncwarp();

        // ---- Spline: all 32 lanes (0-15: dim j0; 16-31: dim j1)
        logdet += spline_pair(P, x, out, jp, jj, myrow, grow);
        __syncwarp();   // P reads retired before next pair's epilogue writes
    }

    // Combine the two half-warp logdet partials and store.
    logdet += __shfl_down_sync(0xffffffffu, logdet, 16);
    if (lane < 16)
        out[(size_t)N * 64 + row0 + myrow] = logdet;
}

// ---------------------------------------------------------------------------
extern "C" void kernel_launch(void* const* d_in, const int* in_sizes, int n_in,
                              void* d_out, int out_size)
{
    const float* x  = (const float*)d_in[0];
    const float* c  = (const float*)d_in[1];
    const float* bs = (const float*)d_in[2];
    const float* bb = (const float*)d_in[3];
    const float* bm = (const float*)d_in[4];
    const float* bv = (const float*)d_in[5];
    const float* W0 = (const float*)d_in[6];
    const float* b0 = (const float*)d_in[7];
    const float* W1 = (const float*)d_in[8];
    const float* b1 = (const float*)d_in[9];
    const float* W2 = (const float*)d_in[10];
    const float* b2 = (const float*)d_in[11];
    float* out = (float*)d_out;

    int N = in_sizes[0] / 64;

    cudaFuncSetAttribute(k_fused, cudaFuncAttributeMaxDynamicSharedMemorySize, (int)SM_TOT);

    k_prep<<<(32 * 6144 + 255) / 256, 256>>>(W0, W1, W2, b2, bs, bb, bm, bv);
    k_fused<<<N / 128, 256, SM_TOT>>>(x, c, b0, b1, out, N);
}

// round 16
// speedup vs baseline: 1.0687x; 1.0055x over previous
#include <cuda_runtime.h>
#include <cuda_fp16.h>
#include <math.h>
#include <stdint.h>

#define SA 136                    // stride (halves) for 128-k tiles
#define S0 56                     // stride (halves) for 48-k tiles
#define PW 108                    // P stride (floats); dim1 at +52

// ---- smem byte offsets ----
#define O_A1H  0u
#define O_A1L  34816u
#define O_W1   69632u
#define O_A0H  69632u
#define O_A0L  83968u
#define O_W0   98304u             // W0 staging ends at 112640
#define O_P    0u                 // 128 x 108 f32 = 55296 (overlays dead A1H/A1L)
#define SM_TOT 112640u

// Pre-converted weights / params (k_prep)
__device__ __half g_w0t[128 * S0];      // W0 n-major [n][k], k<48
__device__ __half g_w1t[128 * SA];      // W1 n-major [n][k], k<128
// W2 in mma-fragment-major order: per dim j (32): 8 ks x 3 tile-pairs x 32
// lanes x 8 halves (16B). One LDG.128 per lane = the 4 B-regs of 2 n-tiles.
__device__ __align__(16) __half g_w2f[32 * 6144];
__device__ float  g_b2p[32 * 48];       // padded b2
__device__ float  g_ab[96];             // BN alpha[48], beta[48]

__device__ __forceinline__ float swishf(float v) {
    return __fdividef(v, 1.0f + __expf(-v));
}

__device__ __forceinline__ void split_fp16(float v, __half* h, __half* l) {
    __half hh = __float2half_rn(v);
    *h = hh;
    *l = __float2half_rn(v - __half2float(hh));
}

__device__ __forceinline__ void mma16816(float* c, const uint32_t* a,
                                         uint32_t b0, uint32_t b1) {
    asm volatile(
        "mma.sync.aligned.m16n8k16.row.col.f32.f16.f16.f32 "
        "{%0,%1,%2,%3}, {%4,%5,%6,%7}, {%8,%9}, {%0,%1,%2,%3};"
        : "+f"(c[0]), "+f"(c[1]), "+f"(c[2]), "+f"(c[3])
        : "r"(a[0]), "r"(a[1]), "r"(a[2]), "r"(a[3]), "r"(b0), "r"(b1));
}

#define LDSM4(d, addr)                                                       \
    asm volatile("ldmatrix.sync.aligned.m8n8.x4.shared.b16 {%0,%1,%2,%3}, [%4];" \
        : "=r"((d)[0]), "=r"((d)[1]), "=r"((d)[2]), "=r"((d)[3]) : "r"(addr))

#define CPASYNC16(dst, src) \
    asm volatile("cp.async.cg.shared.global [%0], [%1], 16;" :: "r"(dst), "l"(src) : "memory")

__device__ __forceinline__ uint32_t smem_u32(const void* p) {
    uint32_t a;
    asm("{ .reg .u64 t; cvta.to.shared.u64 t, %1; cvt.u32.u64 %0, t; }" : "=r"(a) : "l"(p));
    return a;
}

// ---------------------------------------------------------------------------
// Spline for one pair (all 32 lanes: 0-15 -> dim 2jp, 16-31 -> dim 2jp+1).
// float4 loads for ew/eh; sums computed in registers (round-12 order).
// ---------------------------------------------------------------------------
__device__ __forceinline__ float spline_pair(const float* __restrict__ P,
                                             const float* __restrict__ x,
                                             float* __restrict__ out,
                                             int jp, int jj, int myrow,
                                             size_t grow)
{
    const int j = 2 * jp + jj;
    const float* pr = &P[myrow * PW + jj * 52];
    const float4* pr4 = (const float4*)pr;
    float tin = __ldg(&x[grow * 64 + j]);

    float ew[16], eh[16];
    #pragma unroll
    for (int q = 0; q < 4; q++) {
        float4 a4 = pr4[q];
        ew[4 * q + 0] = a4.x; ew[4 * q + 1] = a4.y;
        ew[4 * q + 2] = a4.z; ew[4 * q + 3] = a4.w;
        float4 b4 = pr4[4 + q];
        eh[4 * q + 0] = b4.x; eh[4 * q + 1] = b4.y;
        eh[4 * q + 2] = b4.z; eh[4 * q + 3] = b4.w;
    }

    float sW = 0.0f, sH = 0.0f;
    #pragma unroll
    for (int i = 0; i < 16; i++) { sW += ew[i]; sH += eh[i]; }
    float invW = __fdividef(1.0f, sW);
    float invH = __fdividef(1.0f, sH);

    float tc  = fminf(fmaxf(tin, 0.0f), 1.0f);
    bool  inb = (tin >= 0.0f) && (tin <= 1.0f);

    float xk = 0.0f, cy = 0.0f;
    float xk_b = 0.0f, yk_b = 0.0f;
    float dx_b = ew[0] * invW, dy_b = eh[0] * invH;
    int bidx = 0;
    #pragma unroll
    for (int i = 0; i < 16; i++) {
        float dxi = ew[i] * invW;
        float dyi = eh[i] * invH;
        if (xk <= tc) { bidx = i; xk_b = xk; dx_b = dxi; yk_b = cy; dy_b = dyi; }
        xk += dxi; cy += dyi;
    }

    float v0 = pr[32 + ((bidx > 0) ? bidx - 1 : 0)];
    float v1 = pr[32 + ((bidx < 15) ? bidx : 14)];
    float sp0 = fmaxf(v0, 0.0f) + __logf(1.0f + __expf(-fabsf(v0)));
    float sp1 = fmaxf(v1, 0.0f) + __logf(1.0f + __expf(-fabsf(v1)));
    float d0 = (bidx == 0)  ? 1.0f : sp0;
    float d1 = (bidx == 15) ? 1.0f : sp1;

    float xi   = __fdividef(tc - xk_b, dx_b);
    float s    = __fdividef(dy_b, dx_b);
    float xi1m = xi * (1.0f - xi);
    float den  = s + (d0 + d1 - 2.0f * s) * xi1m;
    float num  = s * xi * xi + d0 * xi1m;
    float y_in = yk_b + dy_b * __fdividef(num, den);
    float omxi = 1.0f - xi;
    float dnum = d1 * xi * xi + 2.0f * s * xi1m + d0 * omxi * omxi;
    float dydx = __fdividef(s * s * dnum, den * den);

    out[grow * 64 + j] = inb ? y_in : tin;
    return inb ? __logf(dydx) : 0.0f;
}

// ---------------------------------------------------------------------------
// Prep: W0/W1 fp16 tiles, W2 fragment-major fp16, BN coeffs, padded bias
// ---------------------------------------------------------------------------
__global__ __launch_bounds__(256)
void k_prep(const float* __restrict__ W0, const float* __restrict__ W1,
            const float* __restrict__ W2, const float* __restrict__ b2,
            const float* __restrict__ bn_scale, const float* __restrict__ bn_bias,
            const float* __restrict__ bn_mean, const float* __restrict__ bn_var)
{
    int idx = blockIdx.x * 256 + threadIdx.x;
    if (idx < 32 * 6144) {               // W2 fragment-major
        int j   = idx / 6144;
        int r   = idx - j * 6144;
        int ks  = r / 768;
        int r2  = r - ks * 768;
        int tp  = r2 / 256;
        int r3  = r2 - tp * 256;
        int ln  = r3 >> 3;
        int h   = r3 & 7;
        int n   = tp * 16 + (ln >> 2) + ((h >= 4) ? 8 : 0);
        int kk  = ks * 16 + 2 * (ln & 3) + (h & 1) + (((h >> 1) & 1) << 3);
        float v = (n < 47) ? W2[(size_t)kk * 1504 + j * 47 + n] : 0.0f;
        g_w2f[idx] = __float2half_rn(v);
    }
    if (idx < 128 * SA) {                // W1 tile
        int n = idx / SA, k = idx - n * SA;
        g_w1t[idx] = (k < 128) ? __float2half_rn(W1[(size_t)k * 128 + n]) : __float2half_rn(0.0f);
    }
    if (idx < 128 * S0) {                // W0 tile
        int n = idx / S0, k = idx - n * S0;
        g_w0t[idx] = (k < 48) ? __float2half_rn(W0[(size_t)k * 128 + n]) : __float2half_rn(0.0f);
    }
    if (idx < 32 * 48) {                 // padded b2
        int j = idx / 48, cc = idx - j * 48;
        g_b2p[idx] = (cc < 47) ? b2[j * 47 + cc] : 0.0f;
    }
    if (idx < 48) {                      // BN coefficients
        float a = bn_scale[idx] * rsqrtf(bn_var[idx] + 1e-5f);
        g_ab[idx]      = a;
        g_ab[48 + idx] = bn_bias[idx] - bn_mean[idx] * a;
    }
}

// ---------------------------------------------------------------------------
// Fused kernel: BN + MLP (fp16 HMMA) + W2 GEMM with the TWO dims of each
// pair INTERLEAVED per k-step (2 independent LDG/MMA streams) + spline.
// No block barriers in the loop. 8 warps x 16 rows, 2 blocks/SM.
// ---------------------------------------------------------------------------
__global__ __launch_bounds__(256, 2)
void k_fused(const float* __restrict__ x, const float* __restrict__ c,
             const float* __restrict__ b0, const float* __restrict__ b1,
             float* __restrict__ out, int N)
{
    extern __shared__ char smem[];
    const uint32_t sb = smem_u32(smem);

    const int tid  = threadIdx.x;
    const int warp = tid >> 5;
    const int lane = tid & 31;
    const int g    = lane >> 2;
    const int c2   = lane & 3;
    const int r0   = warp * 16;
    const int row0 = blockIdx.x * 128;

    // ---- W0 cp.async (896 x 16B)
    {
        const char* src = (const char*)g_w0t;
        #pragma unroll
        for (int it = 0; it < 4; it++) {
            int ch = tid + it * 256;
            if (ch < 896) CPASYNC16(sb + O_W0 + ch * 16, src + ch * 16);
        }
        asm volatile("cp.async.commit_group;" ::: "memory");
    }

    // ---- Stage A0 (BN'd [xc|c]), warp-local rows, fp16 hi/lo; copy xc -> out
    {
        __half* A0h = (__half*)(smem + O_A0H);
        __half* A0l = (__half*)(smem + O_A0L);
        for (int i = lane; i < 16 * 48; i += 32) {
            int r = i / 48, k = i - (i / 48) * 48;
            size_t rg = (size_t)(row0 + r0 + r);
            float v;
            if (k < 32) { v = x[rg * 64 + 32 + k]; out[rg * 64 + 32 + k] = v; }
            else        { v = c[rg * 16 + (k - 32)]; }
            float a = v * g_ab[k] + g_ab[48 + k];
            __half h, l;
            split_fp16(a, &h, &l);
            A0h[(r0 + r) * S0 + k] = h;
            A0l[(r0 + r) * S0 + k] = l;
        }
    }
    asm volatile("cp.async.wait_group 0;" ::: "memory");
    __syncthreads();   // W0 + all A0 rows visible

    // Fragment address components
    const uint32_t a0_off  = (uint32_t)(((r0 + (lane & 15)) * S0 + ((lane >> 4) << 3)) * 2);
    const uint32_t a1_off  = (uint32_t)(((r0 + (lane & 15)) * SA + ((lane >> 4) << 3)) * 2);
    const uint32_t bn0_off = (uint32_t)((((lane & 7) + ((lane >> 4) << 3)) * S0) * 2 + (((lane >> 3) & 1) << 4));
    const uint32_t bn1_off = (uint32_t)((((lane & 7) + ((lane >> 4) << 3)) * SA) * 2 + (((lane >> 3) & 1) << 4));

    // ================= L0: h1 = swish(A0 @ W0 + b0) =====
    {
        float acc[16][4];
        #pragma unroll
        for (int t = 0; t < 16; t++)
            #pragma unroll
            for (int q = 0; q < 4; q++) acc[t][q] = 0.0f;

        const uint32_t a0h_addr = sb + O_A0H + a0_off;
        const uint32_t a0l_addr = sb + O_A0L + a0_off;
        const uint32_t w0_base  = sb + O_W0 + bn0_off;

        #pragma unroll
        for (int ks = 0; ks < 3; ks++) {
            uint32_t ah[4], al[4];
            LDSM4(ah, a0h_addr + ks * 32);
            LDSM4(al, a0l_addr + ks * 32);
            #pragma unroll
            for (int t2 = 0; t2 < 8; t2++) {
                uint32_t bw[4];
                LDSM4(bw, w0_base + t2 * 16 * S0 * 2 + ks * 32);
                mma16816(acc[2 * t2],     ah, bw[0], bw[1]);
                mma16816(acc[2 * t2],     al, bw[0], bw[1]);
                mma16816(acc[2 * t2 + 1], ah, bw[2], bw[3]);
                mma16816(acc[2 * t2 + 1], al, bw[2], bw[3]);
            }
        }

        __half* A1h = (__half*)(smem + O_A1H);
        __half* A1l = (__half*)(smem + O_A1L);
        #pragma unroll
        for (int t = 0; t < 16; t++) {
            int cb = 8 * t + 2 * c2;
            float2 bb = __ldg((const float2*)&b0[cb]);
            float v00 = swishf(acc[t][0] + bb.x), v01 = swishf(acc[t][1] + bb.y);
            float v10 = swishf(acc[t][2] + bb.x), v11 = swishf(acc[t][3] + bb.y);
            __half h0, l0, h1, l1;
            split_fp16(v00, &h0, &l0); split_fp16(v01, &h1, &l1);
            *(__half2*)&A1h[(r0 + g) * SA + cb] = __halves2half2(h0, h1);
            *(__half2*)&A1l[(r0 + g) * SA + cb] = __halves2half2(l0, l1);
            split_fp16(v10, &h0, &l0); split_fp16(v11, &h1, &l1);
            *(__half2*)&A1h[(r0 + g + 8) * SA + cb] = __halves2half2(h0, h1);
            *(__half2*)&A1l[(r0 + g + 8) * SA + cb] = __halves2half2(l0, l1);
        }
    }
    __syncthreads();   // all warps done with A0/W0 region

    // ---- W1 cp.async into (dead) A0/W0 region (2176 x 16B)
    {
        const char* src = (const char*)g_w1t;
        #pragma unroll
        for (int it = 0; it < 9; it++) {
            int ch = tid + it * 256;
            if (ch < 2176) CPASYNC16(sb + O_W1 + ch * 16, src + ch * 16);
        }
        asm volatile("cp.async.commit_group;" ::: "memory");
        asm volatile("cp.async.wait_group 0;" ::: "memory");
    }
    __syncthreads();

    // ================= L1: h2 = swish(A1 @ W1 + b1), K=128 ==================
    uint32_t afh[8][4];    // h2-hi fragments (sole A operand of the W2 GEMM)
    {
        float acc[16][4];
        #pragma unroll
        for (int t = 0; t < 16; t++)
            #pragma unroll
            for (int q = 0; q < 4; q++) acc[t][q] = 0.0f;

        const uint32_t a1h_addr = sb + O_A1H + a1_off;
        const uint32_t a1l_addr = sb + O_A1L + a1_off;
        const uint32_t w1_base  = sb + O_W1 + bn1_off;

        #pragma unroll
        for (int ks = 0; ks < 8; ks++) {
            uint32_t ah[4], al[4];
            LDSM4(ah, a1h_addr + ks * 32);
            LDSM4(al, a1l_addr + ks * 32);
            #pragma unroll
            for (int t2 = 0; t2 < 8; t2++) {
                uint32_t bw[4];
                LDSM4(bw, w1_base + t2 * 16 * SA * 2 + ks * 32);
                mma16816(acc[2 * t2],     ah, bw[0], bw[1]);
                mma16816(acc[2 * t2],     al, bw[0], bw[1]);
                mma16816(acc[2 * t2 + 1], ah, bw[2], bw[3]);
                mma16816(acc[2 * t2 + 1], al, bw[2], bw[3]);
            }
        }
        __syncwarp();   // own A1 rows consumed; safe to overwrite (warp-local)

        // Epilogue: h2-hi only -> staging in O_A1L region
        __half* H2h = (__half*)(smem + O_A1L);
        #pragma unroll
        for (int t = 0; t < 16; t++) {
            int cb = 8 * t + 2 * c2;
            float2 bb = __ldg((const float2*)&b1[cb]);
            float v00 = swishf(acc[t][0] + bb.x), v01 = swishf(acc[t][1] + bb.y);
            float v10 = swishf(acc[t][2] + bb.x), v11 = swishf(acc[t][3] + bb.y);
            *(__half2*)&H2h[(r0 + g) * SA + cb] =
                __halves2half2(__float2half_rn(v00), __float2half_rn(v01));
            *(__half2*)&H2h[(r0 + g + 8) * SA + cb] =
                __halves2half2(__float2half_rn(v10), __float2half_rn(v11));
        }
        __syncwarp();

        const uint32_t h2h_addr = sb + O_A1L + a1_off;
        #pragma unroll
        for (int ks = 0; ks < 8; ks++)
            LDSM4(afh[ks], h2h_addr + ks * 32);
    }
    __syncthreads();   // staging/W1 dead; P region free. LAST block barrier.

    // ================= W2 GEMM + spline loop (no block barriers) ============
    float* P = (float*)(smem + O_P);
    const uint4* w2f = (const uint4*)g_w2f;   // [j][ks][tp][lane] 16B units

    const int jj = lane >> 4;               // 0: dim j0, 1: dim j1 (spline half)
    const int myrow = r0 + (lane & 15);
    const size_t grow = (size_t)(row0 + myrow);

    float logdet = 0.0f;

    for (int jp = 0; jp < 16; jp++) {
        // ---- Interleaved GEMMs for both dims (2 independent streams)
        const uint4* bp0 = w2f + (size_t)(2 * jp) * 768 + lane;
        const uint4* bp1 = bp0 + 768;

        float acc0[6][4], acc1[6][4];
        #pragma unroll
        for (int t = 0; t < 6; t++)
            #pragma unroll
            for (int q = 0; q < 4; q++) { acc0[t][q] = 0.0f; acc1[t][q] = 0.0f; }

        #pragma unroll
        for (int ks = 0; ks < 8; ks++) {
            uint4 p0 = __ldg(bp0 + (ks * 3 + 0) * 32);
            uint4 p1 = __ldg(bp0 + (ks * 3 + 1) * 32);
            uint4 p2 = __ldg(bp0 + (ks * 3 + 2) * 32);
            uint4 q0 = __ldg(bp1 + (ks * 3 + 0) * 32);
            uint4 q1 = __ldg(bp1 + (ks * 3 + 1) * 32);
            uint4 q2 = __ldg(bp1 + (ks * 3 + 2) * 32);
            mma16816(acc0[0], afh[ks], p0.x, p0.y);
            mma16816(acc1[0], afh[ks], q0.x, q0.y);
            mma16816(acc0[1], afh[ks], p0.z, p0.w);
            mma16816(acc1[1], afh[ks], q0.z, q0.w);
            mma16816(acc0[2], afh[ks], p1.x, p1.y);
            mma16816(acc1[2], afh[ks], q1.x, q1.y);
            mma16816(acc0[3], afh[ks], p1.z, p1.w);
            mma16816(acc1[3], afh[ks], q1.z, q1.w);
            mma16816(acc0[4], afh[ks], p2.x, p2.y);
            mma16816(acc1[4], afh[ks], q2.x, q2.y);
            mma16816(acc0[5], afh[ks], p2.z, p2.w);
            mma16816(acc1[5], afh[ks], q2.z, q2.w);
        }

        // ---- Epilogues (bias, exp for softmax cols) -> P halves
        #pragma unroll
        for (int dd = 0; dd < 2; dd++) {
            const int j = 2 * jp + dd;
            const float* bj = &g_b2p[j * 48];
            const int co = dd * 52;
            float (*acc)[4] = dd ? acc1 : acc0;
            #pragma unroll
            for (int t = 0; t < 6; t++) {
                int cb = 8 * t + 2 * c2;
                float2 bb = *(const float2*)&bj[cb];
                float v00 = acc[t][0] + bb.x, v01 = acc[t][1] + bb.y;
                float v10 = acc[t][2] + bb.x, v11 = acc[t][3] + bb.y;
                if (t < 4) {
                    v00 = __expf(v00); v01 = __expf(v01);
                    v10 = __expf(v10); v11 = __expf(v11);
                }
                *(float2*)&P[(r0 + g) * PW + co + cb]     = make_float2(v00, v01);
                *(float2*)&P[(r0 + g + 8) * PW + co + cb] = make_float2(v10, v11);
            }
        }
        __syncwarp();

        // ---- Spline: all 32 lanes (0-15: dim j0; 16-31: dim j1)
        logdet += spline_pair(P, x, out, jp, jj, myrow, grow);
        __syncwarp();   // P reads retired before next pair's epilogue writes
    }

    // Combine the two half-warp logdet partials and store.
    logdet += __shfl_down_sync(0xffffffffu, logdet, 16);
    if (lane < 16)
        out[(size_t)N * 64 + row0 + myrow] = logdet;
}

// ---------------------------------------------------------------------------
extern "C" void kernel_launch(void* const* d_in, const int* in_sizes, int n_in,
                              void* d_out, int out_size)
{
    const float* x  = (const float*)d_in[0];
    const float* c  = (const float*)d_in[1];
    const float* bs = (const float*)d_in[2];
    const float* bb = (const float*)d_in[3];
    const float* bm = (const float*)d_in[4];
    const float* bv = (const float*)d_in[5];
    const float* W0 = (const float*)d_in[6];
    const float* b0 = (const float*)d_in[7];
    const float* W1 = (const float*)d_in[8];
    const float* b1 = (const float*)d_in[9];
    const float* W2 = (const float*)d_in[10];
    const float* b2 = (const float*)d_in[11];
    float* out = (float*)d_out;

    int N = in_sizes[0] / 64;

    cudaFuncSetAttribute(k_fused, cudaFuncAttributeMaxDynamicSharedMemorySize, (int)SM_TOT);

    k_prep<<<(32 * 6144 + 255) / 256, 256>>>(W0, W1, W2, b2, bs, bb, bm, bv);
    k_fused<<<N / 128, 256, SM_TOT>>>(x, c, b0, b1, out, N);
}